// round 9
// baseline (speedup 1.0000x reference)
#include <cuda_runtime.h>

// Problem constants
#define C0   8
#define C1   4
#define GQ   8      // gaussian basis count
#define QI   16
#define QO   16
#define K3   125
#define NI   320    // dim_in * Qi
#define NO   320    // dim_out * Qo
#define VOX  512    // 8*8*8
#define NSPLIT 4    // input-channel split factor (k-split across blocks)

// 51.2 MB scratch for the materialized conv kernel, layout [O][I][tap]
__device__ float g_kern[NO * NI * K3];
// per-split partial sums: [NSPLIT][NO*VOX]
__device__ float g_part[NSPLIT * NO * VOX];

__device__ __forceinline__ float dot8(const float* __restrict__ w, const float* R) {
    float s = 0.f;
#pragma unroll
    for (int g = 0; g < 8; g++) s = fmaf(w[g], R[g], s);
    return s;
}

// ---------------------------------------------------------------------------
// Kernel 1: build kern[O][I][tap].
// grid = (256, 8): blockIdx.x = (p,q) pair; blockIdx.y splits output channels
//   (y<4 -> scalar-out a in {2y, 2y+1}; y>=4 -> vector-out av = y-4).
// 128 threads, tap = threadIdx.x < 125.
// ---------------------------------------------------------------------------
__global__ void __launch_bounds__(128) build_kern_kernel(
    const float* __restrict__ q_in, const float* __restrict__ q_out,
    const float* __restrict__ w_ss, const float* __restrict__ w_vs,
    const float* __restrict__ w_sv, const float* __restrict__ w_vv0,
    const float* __restrict__ w_vv1)
{
    __shared__ float s[1280]; // ss 512 | vs 256 | sv 256 | vv0 128 | vv1 128
    const int t = threadIdx.x;
    for (int j = t; j < 512; j += 128) s[j] = w_ss[j];
    for (int j = t; j < 256; j += 128) { s[512 + j] = w_vs[j]; s[768 + j] = w_sv[j]; }
    if (t < 128) { s[1024 + t] = w_vv0[t]; s[1152 + t] = w_vv1[t]; }
    __syncthreads();
    if (t >= K3) return;

    const int p = blockIdx.x >> 4;
    const int q = blockIdx.x & 15;
    const int kz = t / 25, ky = (t / 5) % 5, kx = t % 5;

    // v = p_off - (q_out[p] - q_in[q]); components ordered (z,y,x) like stack
    const float v0 = (float)(kz - 2) - (q_out[p * 3 + 0] - q_in[q * 3 + 0]);
    const float v1 = (float)(ky - 2) - (q_out[p * 3 + 1] - q_in[q * 3 + 1]);
    const float v2 = (float)(kx - 2) - (q_out[p * 3 + 2] - q_in[q * 3 + 2]);
    const float r  = sqrtf(v0 * v0 + v1 * v1 + v2 * v2);
    const float inv = (r > 1e-6f) ? (1.0f / r) : 0.0f;
    const float u0 = v0 * inv, u1 = v1 * inv, u2 = v2 * inv;

    // gaussian RBF: centers = g*sigma, sigma = 5.5/7
    float R[8];
    const float tt = r * (7.0f / 5.5f);
#pragma unroll
    for (int g = 0; g < 8; g++) {
        float d = tt - (float)g;
        R[g] = expf(-0.5f * d * d);
    }

    // cross-product matrix M[i][j] = eps[i,m,j] u_m
    float M[3][3];
    M[0][0] = 0.f;  M[0][1] = -u2;  M[0][2] =  u1;
    M[1][0] =  u2;  M[1][1] = 0.f;  M[1][2] = -u0;
    M[2][0] = -u1;  M[2][1] =  u0;  M[2][2] = 0.f;
    const float U[3] = {u0, u1, u2};

    const float* sw_ss  = s;
    const float* sw_vs  = s + 512;
    const float* sw_sv  = s + 768;
    const float* sw_vv0 = s + 1024;
    const float* sw_vv1 = s + 1152;

    const int by = blockIdx.y;
    if (by < 4) {
        // scalar-out rows: a in {2*by, 2*by+1}
        for (int a = by * 2; a < by * 2 + 2; a++) {
            const int Obase = (a * QO + p) * NI;
            for (int c = 0; c < C0; c++) {
                float val = dot8(sw_ss + (a * C0 + c) * 8, R);
                g_kern[(Obase + c * QI + q) * K3 + t] = val;
            }
            for (int cv = 0; cv < C1; cv++) {
                float d = dot8(sw_sv + (a * C1 + cv) * 8, R);
#pragma unroll
                for (int n = 0; n < 3; n++) {
                    g_kern[(Obase + (C0 + cv * 3 + n) * QI + q) * K3 + t] = d * U[n];
                }
            }
        }
    } else {
        // vector-out rows for av = by - 4: O = C0 + av*3 + m
        const int av = by - 4;
        for (int c = 0; c < C0; c++) {
            float d = dot8(sw_vs + (av * C0 + c) * 8, R);
#pragma unroll
            for (int m = 0; m < 3; m++) {
                int O = (C0 + av * 3 + m) * QO + p;
                g_kern[(O * NI + c * QI + q) * K3 + t] = d * U[m];
            }
        }
        for (int cv = 0; cv < C1; cv++) {
            float d0 = dot8(sw_vv0 + (av * C1 + cv) * 8, R);
            float d1 = 0.7071067811865476f * dot8(sw_vv1 + (av * C1 + cv) * 8, R);
#pragma unroll
            for (int i = 0; i < 3; i++) {
                int O = (C0 + av * 3 + i) * QO + p;
#pragma unroll
                for (int j = 0; j < 3; j++) {
                    float val = (i == j) ? d0 : d1 * M[i][j];
                    g_kern[(O * NI + (C0 + cv * 3 + j) * QI + q) * K3 + t] = val;
                }
            }
        }
    }
}

// ---------------------------------------------------------------------------
// Kernel 2: 3D conv via packed f32x2 FMA, 4 output channels per lane
// (two f32x2 accumulator sets sharing each x load), k-split over input
// channels into NSPLIT partials, padding FMAs skipped at compile time.
// grid = (160, NSPLIT): blockIdx.x>>1 = out-channel quad, blockIdx.x&1 = z half,
//                       blockIdx.y = input-channel chunk.
// blockDim = 128: warp id g splits the 25 (kz,ky) tap rows (row%4==g);
// lane -> (z_local in [0,4), y in [0,8)); each thread owns a full 8-wide x-row.
// ---------------------------------------------------------------------------
#define FMA2(d, a, b) asm("fma.rn.f32x2 %0, %1, %2, %0;" : "+l"(d) : "l"(a), "l"(b))
#define ADD2(d, a)    asm("add.rn.f32x2 %0, %0, %1;"     : "+l"(d) : "l"(a))

#define XROW 9   // padded row stride (float2 units) -> conflict-free LDS.64
#define IBLK 2
#define NICHUNK (NI / NSPLIT)   // 80

__global__ void __launch_bounds__(128, 5) conv_kernel(const float* __restrict__ x)
{
    __shared__ __align__(16) float2 xs[IBLK][64 * XROW];  // duplicated {x,x}
    __shared__ __align__(16) float  ks[IBLK][128 * 4];    // {k0,k1,k2,k3} per tap
    __shared__ __align__(16) unsigned long long red[3][32][16];

    const int t    = threadIdx.x;
    const int g    = t >> 5;
    const int lane = t & 31;
    const int o0   = (blockIdx.x >> 1) * 4;
    const int zh   = blockIdx.x & 1;
    const int spl  = blockIdx.y;
    const int z    = zh * 4 + (lane >> 3);
    const int y    = lane & 7;

    unsigned long long acc0[8], acc1[8];
#pragma unroll
    for (int ox = 0; ox < 8; ox++) { acc0[ox] = 0ull; acc1[ox] = 0ull; }

    const float* kp0 = g_kern + (size_t)o0 * (NI * K3);

    const int ib0 = spl * NICHUNK;
    for (int ib = ib0; ib < ib0 + NICHUNK; ib += IBLK) {
#pragma unroll
        for (int ii = 0; ii < IBLK; ii++) {
#pragma unroll
            for (int j = 0; j < 4; j++) {
                int idx = t + 128 * j;
                float xv = x[(ib + ii) * VOX + idx];
                xs[ii][(idx >> 3) * XROW + (idx & 7)] = make_float2(xv, xv);
            }
            if (t < K3) {
                const float* kb = kp0 + (ib + ii) * K3 + t;
                float k0 = kb[0];
                float k1 = kb[NI * K3];
                float k2 = kb[2 * NI * K3];
                float k3 = kb[3 * NI * K3];
                *reinterpret_cast<float4*>(&ks[ii][t * 4]) =
                    make_float4(k0, k1, k2, k3);
            }
        }
        __syncthreads();

#pragma unroll
        for (int ii = 0; ii < IBLK; ii++) {
            const unsigned long long* xb =
                reinterpret_cast<const unsigned long long*>(xs[ii]);
            const unsigned long long* kb =
                reinterpret_cast<const unsigned long long*>(ks[ii]);
#pragma unroll 1
            for (int row = g; row < 25; row += 4) {
                int kz = row / 5, ky = row - kz * 5;
                int zi = z + kz - 2, yi = y + ky - 2;
                if (((unsigned)zi < 8u) & ((unsigned)yi < 8u)) {
                    const unsigned long long* xr = xb + (zi * 8 + yi) * XROW;
                    unsigned long long xp[8];
#pragma unroll
                    for (int j = 0; j < 8; j++) xp[j] = xr[j];
                    const unsigned long long* kr = kb + row * 10;
#pragma unroll
                    for (int kx = 0; kx < 5; kx++) {
                        unsigned long long k01 = kr[kx * 2];
                        unsigned long long k23 = kr[kx * 2 + 1];
#pragma unroll
                        for (int ox = 0; ox < 8; ox++) {
                            const int xi = ox + kx - 2;
                            if (xi >= 0 && xi < 8) {
                                FMA2(acc0[ox], k01, xp[xi]);
                                FMA2(acc1[ox], k23, xp[xi]);
                            }
                        }
                    }
                }
            }
        }
        __syncthreads();
    }

    // reduce the 4 warp-partials for each (z,y)
    if (g != 0) {
#pragma unroll
        for (int ox = 0; ox < 8; ox++) {
            red[g - 1][lane][ox]     = acc0[ox];
            red[g - 1][lane][8 + ox] = acc1[ox];
        }
    }
    __syncthreads();
    if (g == 0) {
#pragma unroll
        for (int j = 0; j < 3; j++) {
#pragma unroll
            for (int ox = 0; ox < 8; ox++) {
                ADD2(acc0[ox], red[j][lane][ox]);
                ADD2(acc1[ox], red[j][lane][8 + ox]);
            }
        }
        const int vox = z * 64 + y * 8;
        float* p0 = g_part + (size_t)spl * (NO * VOX) + (size_t)o0 * VOX + vox;
#pragma unroll
        for (int ox = 0; ox < 8; ox++) {
            float2 r0 = *reinterpret_cast<float2*>(&acc0[ox]);
            float2 r1 = *reinterpret_cast<float2*>(&acc1[ox]);
            p0[ox]           = r0.x;
            p0[VOX + ox]     = r0.y;
            p0[2 * VOX + ox] = r1.x;
            p0[3 * VOX + ox] = r1.y;
        }
    }
}

// ---------------------------------------------------------------------------
// Kernel 3: sum the NSPLIT partials + bias -> out
// ---------------------------------------------------------------------------
__global__ void __launch_bounds__(256) reduce_kernel(
    const float* __restrict__ bias, float* __restrict__ out)
{
    const int idx = blockIdx.x * 256 + threadIdx.x;   // [0, NO*VOX)
    float s = 0.f;
#pragma unroll
    for (int sp = 0; sp < NSPLIT; sp++) s += g_part[sp * (NO * VOX) + idx];
    const int o = idx >> 9;                           // output channel [0,320)
    const float b = (o < C0 * QO) ? bias[o >> 4] : 0.0f;
    out[idx] = s + b;
}

// ---------------------------------------------------------------------------
extern "C" void kernel_launch(void* const* d_in, const int* in_sizes, int n_in,
                              void* d_out, int out_size)
{
    (void)in_sizes; (void)n_in; (void)out_size;
    const float* x     = (const float*)d_in[0];
    const float* q_in  = (const float*)d_in[1];
    const float* q_out = (const float*)d_in[2];
    const float* w_ss  = (const float*)d_in[3];
    const float* w_vs  = (const float*)d_in[4];
    const float* w_sv  = (const float*)d_in[5];
    const float* w_vv0 = (const float*)d_in[6];
    const float* w_vv1 = (const float*)d_in[7];
    const float* bias  = (const float*)d_in[8];
    float* out = (float*)d_out;

    build_kern_kernel<<<dim3(QO * QI, 8), 128>>>(q_in, q_out, w_ss, w_vs, w_sv,
                                                 w_vv0, w_vv1);
    conv_kernel<<<dim3(160, NSPLIT), 128>>>(x);
    reduce_kernel<<<(NO * VOX) / 256, 256>>>(bias, out);
}

// round 10
// speedup vs baseline: 1.0019x; 1.0019x over previous
#include <cuda_runtime.h>

// Problem constants
#define C0   8
#define C1   4
#define GQ   8      // gaussian basis count
#define QI   16
#define QO   16
#define K3   125
#define NI   320    // dim_in * Qi
#define NO   320    // dim_out * Qo
#define VOX  512    // 8*8*8
#define NSPLIT 4    // input-channel split factor (k-split across blocks)

// 51.2 MB scratch for the materialized conv kernel, layout [O][I][tap]
__device__ float g_kern[NO * NI * K3];
// per-split partial sums: [NSPLIT][NO*VOX]
__device__ float g_part[NSPLIT * NO * VOX];

__device__ __forceinline__ float dot8(const float* __restrict__ w, const float* R) {
    float s = 0.f;
#pragma unroll
    for (int g = 0; g < 8; g++) s = fmaf(w[g], R[g], s);
    return s;
}

// ---------------------------------------------------------------------------
// Kernel 1: build kern[O][I][tap].
// grid = (256, 8): blockIdx.x = (p,q) pair; blockIdx.y splits output channels
//   (y<4 -> scalar-out a in {2y, 2y+1}; y>=4 -> vector-out av = y-4).
// 128 threads, tap = threadIdx.x < 125.
// ---------------------------------------------------------------------------
__global__ void __launch_bounds__(128) build_kern_kernel(
    const float* __restrict__ q_in, const float* __restrict__ q_out,
    const float* __restrict__ w_ss, const float* __restrict__ w_vs,
    const float* __restrict__ w_sv, const float* __restrict__ w_vv0,
    const float* __restrict__ w_vv1)
{
    __shared__ float s[1280]; // ss 512 | vs 256 | sv 256 | vv0 128 | vv1 128
    const int t = threadIdx.x;
    for (int j = t; j < 512; j += 128) s[j] = w_ss[j];
    for (int j = t; j < 256; j += 128) { s[512 + j] = w_vs[j]; s[768 + j] = w_sv[j]; }
    if (t < 128) { s[1024 + t] = w_vv0[t]; s[1152 + t] = w_vv1[t]; }
    __syncthreads();
    if (t >= K3) return;

    const int p = blockIdx.x >> 4;
    const int q = blockIdx.x & 15;
    const int kz = t / 25, ky = (t / 5) % 5, kx = t % 5;

    // v = p_off - (q_out[p] - q_in[q]); components ordered (z,y,x) like stack
    const float v0 = (float)(kz - 2) - (q_out[p * 3 + 0] - q_in[q * 3 + 0]);
    const float v1 = (float)(ky - 2) - (q_out[p * 3 + 1] - q_in[q * 3 + 1]);
    const float v2 = (float)(kx - 2) - (q_out[p * 3 + 2] - q_in[q * 3 + 2]);
    const float r  = sqrtf(v0 * v0 + v1 * v1 + v2 * v2);
    const float inv = (r > 1e-6f) ? (1.0f / r) : 0.0f;
    const float u0 = v0 * inv, u1 = v1 * inv, u2 = v2 * inv;

    // gaussian RBF: centers = g*sigma, sigma = 5.5/7
    float R[8];
    const float tt = r * (7.0f / 5.5f);
#pragma unroll
    for (int g = 0; g < 8; g++) {
        float d = tt - (float)g;
        R[g] = expf(-0.5f * d * d);
    }

    // cross-product matrix M[i][j] = eps[i,m,j] u_m
    float M[3][3];
    M[0][0] = 0.f;  M[0][1] = -u2;  M[0][2] =  u1;
    M[1][0] =  u2;  M[1][1] = 0.f;  M[1][2] = -u0;
    M[2][0] = -u1;  M[2][1] =  u0;  M[2][2] = 0.f;
    const float U[3] = {u0, u1, u2};

    const float* sw_ss  = s;
    const float* sw_vs  = s + 512;
    const float* sw_sv  = s + 768;
    const float* sw_vv0 = s + 1024;
    const float* sw_vv1 = s + 1152;

    const int by = blockIdx.y;
    if (by < 4) {
        // scalar-out rows: a in {2*by, 2*by+1}
        for (int a = by * 2; a < by * 2 + 2; a++) {
            const int Obase = (a * QO + p) * NI;
            for (int c = 0; c < C0; c++) {
                float val = dot8(sw_ss + (a * C0 + c) * 8, R);
                g_kern[(Obase + c * QI + q) * K3 + t] = val;
            }
            for (int cv = 0; cv < C1; cv++) {
                float d = dot8(sw_sv + (a * C1 + cv) * 8, R);
#pragma unroll
                for (int n = 0; n < 3; n++) {
                    g_kern[(Obase + (C0 + cv * 3 + n) * QI + q) * K3 + t] = d * U[n];
                }
            }
        }
    } else {
        // vector-out rows for av = by - 4: O = C0 + av*3 + m
        const int av = by - 4;
        for (int c = 0; c < C0; c++) {
            float d = dot8(sw_vs + (av * C0 + c) * 8, R);
#pragma unroll
            for (int m = 0; m < 3; m++) {
                int O = (C0 + av * 3 + m) * QO + p;
                g_kern[(O * NI + c * QI + q) * K3 + t] = d * U[m];
            }
        }
        for (int cv = 0; cv < C1; cv++) {
            float d0 = dot8(sw_vv0 + (av * C1 + cv) * 8, R);
            float d1 = 0.7071067811865476f * dot8(sw_vv1 + (av * C1 + cv) * 8, R);
#pragma unroll
            for (int i = 0; i < 3; i++) {
                int O = (C0 + av * 3 + i) * QO + p;
#pragma unroll
                for (int j = 0; j < 3; j++) {
                    float val = (i == j) ? d0 : d1 * M[i][j];
                    g_kern[(O * NI + (C0 + cv * 3 + j) * QI + q) * K3 + t] = val;
                }
            }
        }
    }
}

// ---------------------------------------------------------------------------
// Kernel 2: 3D conv via packed f32x2 FMA, 4 output channels per lane
// (two f32x2 accumulator sets sharing each x load), k-split over input
// channels into NSPLIT partials, padding FMAs skipped at compile time.
// grid = (160, NSPLIT): blockIdx.x>>1 = out-channel quad, blockIdx.x&1 = z half,
//                       blockIdx.y = input-channel chunk.
// blockDim = 128: warp id g splits the 25 (kz,ky) tap rows (row%4==g);
// lane -> (z_local in [0,4), y in [0,8)); each thread owns a full 8-wide x-row.
// ---------------------------------------------------------------------------
#define FMA2(d, a, b) asm("fma.rn.f32x2 %0, %1, %2, %0;" : "+l"(d) : "l"(a), "l"(b))
#define ADD2(d, a)    asm("add.rn.f32x2 %0, %0, %1;"     : "+l"(d) : "l"(a))

#define XROW 9   // padded row stride (float2 units) -> conflict-free LDS.64
#define IBLK 2
#define NICHUNK (NI / NSPLIT)   // 80

__global__ void __launch_bounds__(128, 5) conv_kernel(const float* __restrict__ x)
{
    __shared__ __align__(16) float2 xs[IBLK][64 * XROW];  // duplicated {x,x}
    __shared__ __align__(16) float  ks[IBLK][128 * 4];    // {k0,k1,k2,k3} per tap
    __shared__ __align__(16) unsigned long long red[3][32][16];

    const int t    = threadIdx.x;
    const int g    = t >> 5;
    const int lane = t & 31;
    const int o0   = (blockIdx.x >> 1) * 4;
    const int zh   = blockIdx.x & 1;
    const int spl  = blockIdx.y;
    const int z    = zh * 4 + (lane >> 3);
    const int y    = lane & 7;

    unsigned long long acc0[8], acc1[8];
#pragma unroll
    for (int ox = 0; ox < 8; ox++) { acc0[ox] = 0ull; acc1[ox] = 0ull; }

    const float* kp0 = g_kern + (size_t)o0 * (NI * K3);

    const int ib0 = spl * NICHUNK;
    for (int ib = ib0; ib < ib0 + NICHUNK; ib += IBLK) {
#pragma unroll
        for (int ii = 0; ii < IBLK; ii++) {
#pragma unroll
            for (int j = 0; j < 4; j++) {
                int idx = t + 128 * j;
                float xv = x[(ib + ii) * VOX + idx];
                xs[ii][(idx >> 3) * XROW + (idx & 7)] = make_float2(xv, xv);
            }
            if (t < K3) {
                const float* kb = kp0 + (ib + ii) * K3 + t;
                float k0 = kb[0];
                float k1 = kb[NI * K3];
                float k2 = kb[2 * NI * K3];
                float k3 = kb[3 * NI * K3];
                *reinterpret_cast<float4*>(&ks[ii][t * 4]) =
                    make_float4(k0, k1, k2, k3);
            }
        }
        __syncthreads();

#pragma unroll
        for (int ii = 0; ii < IBLK; ii++) {
            const unsigned long long* xb =
                reinterpret_cast<const unsigned long long*>(xs[ii]);
            const unsigned long long* kb =
                reinterpret_cast<const unsigned long long*>(ks[ii]);
#pragma unroll 1
            for (int row = g; row < 25; row += 4) {
                int kz = row / 5, ky = row - kz * 5;
                int zi = z + kz - 2, yi = y + ky - 2;
                if (((unsigned)zi < 8u) & ((unsigned)yi < 8u)) {
                    const unsigned long long* xr = xb + (zi * 8 + yi) * XROW;
                    unsigned long long xp[8];
#pragma unroll
                    for (int j = 0; j < 8; j++) xp[j] = xr[j];
                    const unsigned long long* kr = kb + row * 10;
#pragma unroll
                    for (int kx = 0; kx < 5; kx++) {
                        unsigned long long k01 = kr[kx * 2];
                        unsigned long long k23 = kr[kx * 2 + 1];
#pragma unroll
                        for (int ox = 0; ox < 8; ox++) {
                            const int xi = ox + kx - 2;
                            if (xi >= 0 && xi < 8) {
                                FMA2(acc0[ox], k01, xp[xi]);
                                FMA2(acc1[ox], k23, xp[xi]);
                            }
                        }
                    }
                }
            }
        }
        __syncthreads();
    }

    // reduce the 4 warp-partials for each (z,y)
    if (g != 0) {
#pragma unroll
        for (int ox = 0; ox < 8; ox++) {
            red[g - 1][lane][ox]     = acc0[ox];
            red[g - 1][lane][8 + ox] = acc1[ox];
        }
    }
    __syncthreads();
    if (g == 0) {
#pragma unroll
        for (int j = 0; j < 3; j++) {
#pragma unroll
            for (int ox = 0; ox < 8; ox++) {
                ADD2(acc0[ox], red[j][lane][ox]);
                ADD2(acc1[ox], red[j][lane][8 + ox]);
            }
        }
        const int vox = z * 64 + y * 8;
        float* p0 = g_part + (size_t)spl * (NO * VOX) + (size_t)o0 * VOX + vox;
#pragma unroll
        for (int ox = 0; ox < 8; ox++) {
            float2 r0 = *reinterpret_cast<float2*>(&acc0[ox]);
            float2 r1 = *reinterpret_cast<float2*>(&acc1[ox]);
            p0[ox]           = r0.x;
            p0[VOX + ox]     = r0.y;
            p0[2 * VOX + ox] = r1.x;
            p0[3 * VOX + ox] = r1.y;
        }
    }
}

// ---------------------------------------------------------------------------
// Kernel 3: sum the NSPLIT partials + bias -> out
// ---------------------------------------------------------------------------
__global__ void __launch_bounds__(256) reduce_kernel(
    const float* __restrict__ bias, float* __restrict__ out)
{
    const int idx = blockIdx.x * 256 + threadIdx.x;   // [0, NO*VOX)
    float s = 0.f;
#pragma unroll
    for (int sp = 0; sp < NSPLIT; sp++) s += g_part[sp * (NO * VOX) + idx];
    const int o = idx >> 9;                           // output channel [0,320)
    const float b = (o < C0 * QO) ? bias[o >> 4] : 0.0f;
    out[idx] = s + b;
}

// ---------------------------------------------------------------------------
extern "C" void kernel_launch(void* const* d_in, const int* in_sizes, int n_in,
                              void* d_out, int out_size)
{
    (void)in_sizes; (void)n_in; (void)out_size;
    const float* x     = (const float*)d_in[0];
    const float* q_in  = (const float*)d_in[1];
    const float* q_out = (const float*)d_in[2];
    const float* w_ss  = (const float*)d_in[3];
    const float* w_vs  = (const float*)d_in[4];
    const float* w_sv  = (const float*)d_in[5];
    const float* w_vv0 = (const float*)d_in[6];
    const float* w_vv1 = (const float*)d_in[7];
    const float* bias  = (const float*)d_in[8];
    float* out = (float*)d_out;

    build_kern_kernel<<<dim3(QO * QI, 8), 128>>>(q_in, q_out, w_ss, w_vs, w_sv,
                                                 w_vv0, w_vv1);
    conv_kernel<<<dim3(160, NSPLIT), 128>>>(x);
    reduce_kernel<<<(NO * VOX) / 256, 256>>>(bias, out);
}